// round 16
// baseline (speedup 1.0000x reference)
#include <cuda_runtime.h>
#include <cuda_fp16.h>
#include <cuda_bf16.h>
#include <cstdint>

// Problem constants
#define B_    64
#define Q_    900
#define T_    256
#define L_    769
#define LP    776            // padded row stride (16B-aligned rows of half)
#define NSEL  50
#define M_    (B_ * Q_)      // 57600
#define CCAP  8192
#define NSL   32             // ladder levels (0.25 steps, down to max-8)
#define CMINC 256u           // min chunk count above tau
#define RS2_CAP 2048
#define NCH   97             // 8-wide chunks per row (769 -> 97)
#define CPAD  104            // padded cmax row stride (16B aligned)

// Scratch (static device globals; allocation-free)
__device__ __nv_bfloat16  g_sig_b[(size_t)M_ * T_];    // bf16 sigmoid, 29.5 MB
__device__ __nv_bfloat16  g_pos_b[(size_t)L_ * T_];    // bf16 posmap
__device__ __half         g_prob_h[(size_t)M_ * LP];   // approx prob fp16, 89 MB
__device__ __half         g_cmax[(size_t)M_ * CPAD];   // per-chunk max, 12 MB
__device__ unsigned       g_maxbits[B_];               // per-batch max (uint bits)
__device__ unsigned       g_scnt[B_][NSL];             // chunk ladder counts
__device__ float          g_tau[B_];
__device__ int            g_ccnt[B_];
__device__ int            g_cand[B_][CCAP];            // candidate flat idx (q*L+l)
__device__ __half         g_cval[B_][CCAP];            // candidate approx value

__constant__ int c_tok[80] = {
    0, 9, 19, 25, 38, 49, 55, 63, 71, 78, 94, 109, 121, 137, 145, 152,
    158, 164, 172, 180, 186, 197, 204, 212, 222, 233, 244, 254, 260, 271,
    281, 288, 300, 314, 321, 336, 353, 366, 378, 394, 403, 416, 422, 429,
    437, 445, 452, 461, 469, 480, 489, 500, 509, 519, 527, 535, 542, 550,
    558, 573, 579, 594, 603, 608, 617, 625, 634, 645, 658, 670, 677, 687,
    694, 709, 716, 724, 731, 742, 755, 768};

// ---------------------------------------------------------------------------
// Helpers
// ---------------------------------------------------------------------------
__device__ __forceinline__ uint32_t smem_u32(const void* p) {
    uint32_t a;
    asm("{ .reg .u64 t; cvta.to.shared.u64 t, %1; cvt.u32.u64 %0, t; }" : "=r"(a) : "l"(p));
    return a;
}
__device__ __forceinline__ void cp_async16(uint32_t dst, const void* src, bool valid) {
    int sz = valid ? 16 : 0;   // src-size 0 => zero-fill 16B
    asm volatile("cp.async.cg.shared.global [%0], [%1], 16, %2;\n"
                 :: "r"(dst), "l"(src), "r"(sz));
}
__device__ __forceinline__ void cp_commit() { asm volatile("cp.async.commit_group;"); }
template <int N> __device__ __forceinline__ void cp_wait() {
    asm volatile("cp.async.wait_group %0;" :: "n"(N));
}
__device__ __forceinline__ void ldmatrix_x4(uint32_t* f, uint32_t addr) {
    asm volatile("ldmatrix.sync.aligned.m8n8.x4.shared.b16 {%0,%1,%2,%3}, [%4];"
                 : "=r"(f[0]), "=r"(f[1]), "=r"(f[2]), "=r"(f[3]) : "r"(addr));
}
__device__ __forceinline__ void mma_bf16(float* d, const uint32_t* a,
                                         uint32_t b0, uint32_t b1) {
    asm volatile(
        "mma.sync.aligned.m16n8k16.row.col.f32.bf16.bf16.f32 "
        "{%0,%1,%2,%3}, {%4,%5,%6,%7}, {%8,%9}, {%0,%1,%2,%3};"
        : "+f"(d[0]), "+f"(d[1]), "+f"(d[2]), "+f"(d[3])
        : "r"(a[0]), "r"(a[1]), "r"(a[2]), "r"(a[3]), "r"(b0), "r"(b1));
}
__device__ __forceinline__ float sigf(float x) {
    return 1.0f / (1.0f + __expf(-x));
}

// ---------------------------------------------------------------------------
// Kernel 0: reset counters only
// ---------------------------------------------------------------------------
__global__ void zero_kernel() {
    int i = blockIdx.x * blockDim.x + threadIdx.x;
    if (i < B_) { g_ccnt[i] = 0; g_maxbits[i] = 0u; }
    if (i < B_ * NSL) ((unsigned*)g_scnt)[i] = 0u;
}

// ---------------------------------------------------------------------------
// Kernel 1: sigmoid -> bf16 ; 1b: posmap -> bf16
// ---------------------------------------------------------------------------
__global__ void sigmoid_kernel(const float* __restrict__ x, int n4) {
    int i = blockIdx.x * blockDim.x + threadIdx.x;
    if (i < n4) {
        float4 v = reinterpret_cast<const float4*>(x)[i];
        __nv_bfloat162* o = reinterpret_cast<__nv_bfloat162*>(g_sig_b) + 2 * i;
        o[0] = __floats2bfloat162_rn(sigf(v.x), sigf(v.y));
        o[1] = __floats2bfloat162_rn(sigf(v.z), sigf(v.w));
    }
}

__global__ void posconv_kernel(const float* __restrict__ p, int n2) {
    int i = blockIdx.x * blockDim.x + threadIdx.x;
    if (i < n2) {
        float2 v = reinterpret_cast<const float2*>(p)[i];
        reinterpret_cast<__nv_bfloat162*>(g_pos_b)[i] = __floats2bfloat162_rn(v.x, v.y);
    }
}

// ---------------------------------------------------------------------------
// Kernel 2: bf16 mma.sync GEMM, CTA 128x128, BK=32.
// 4-buffer depth-2 cp.async pipeline (64KB smem) + __launch_bounds__(256,3)
// => 3 CTAs/SM (24 warps) for latency hiding.
// Epilogue: smem-staged coalesced prob/cmax writeout + batch max.
// ---------------------------------------------------------------------------
#define STG_BYTES 16384
#define NSTG 8   // 256/32 k-stages
#define NBUF 4
#define SSTR 136  // stage row stride in halves (272B: 4-bank shift per row)

__global__ __launch_bounds__(256, 3) void gemm_kernel() {
    extern __shared__ char dsm[];
    const uint32_t sbase = smem_u32(dsm);
    __shared__ unsigned s_mx0, s_mx1;
    const int tid  = threadIdx.x;
    const int wid  = tid >> 5;
    const int lane = tid & 31;
    const int wm   = wid & 3;      // 0..3 (m)
    const int wn   = wid >> 2;     // 0..1 (n)
    const int m0   = blockIdx.x * 128;
    const int l0   = blockIdx.y * 128;

    if (tid == 0) { s_mx0 = 0u; s_mx1 = 0u; }

    float acc[2][8][4];
#pragma unroll
    for (int a = 0; a < 2; a++)
#pragma unroll
        for (int b = 0; b < 8; b++)
#pragma unroll
            for (int c = 0; c < 4; c++) acc[a][b][c] = 0.0f;

    auto load_stage = [&](int s) {
        const uint32_t base = sbase + (s & (NBUF - 1)) * STG_BYTES;
        const int k0 = s * 32;
#pragma unroll
        for (int t = 0; t < 2; t++) {              // A
            int ch = tid + t * 256;
            int r  = ch >> 2;
            int cc = ch & 3;
            int ph = cc ^ ((r >> 1) & 3);
            cp_async16(base + r * 64 + ph * 16,
                       g_sig_b + (size_t)(m0 + r) * T_ + k0 + cc * 8, true);
        }
#pragma unroll
        for (int t = 0; t < 2; t++) {              // B
            int ch = tid + t * 256;
            int r  = ch >> 2;
            int cc = ch & 3;
            int ph = cc ^ ((r >> 1) & 3);
            bool ok = (l0 + r) < L_;
            cp_async16(base + 8192 + r * 64 + ph * 16,
                       g_pos_b + (size_t)(l0 + r) * T_ + k0 + cc * 8, ok);
        }
        cp_commit();
    };

    load_stage(0);
    load_stage(1);

    const int j  = lane >> 3;
    const int r8 = lane & 7;

    for (int s = 0; s < NSTG; s++) {
        // Depth-2: issue load(s+2) first; pending = {s, s+1, s+2};
        // wait_group 2 retires stage s. Buffer (s+2)&3 last read at s-2: safe
        // (all warps passed the s-1 barrier which follows s-2 compute).
        if (s + 2 < NSTG)      { load_stage(s + 2); cp_wait<2>(); }
        else if (s + 1 < NSTG) cp_wait<1>();
        else                   cp_wait<0>();
        __syncthreads();

        const uint32_t ab = sbase + (s & (NBUF - 1)) * STG_BYTES;
        const uint32_t bb = ab + 8192;

#pragma unroll
        for (int ks = 0; ks < 2; ks++) {
            uint32_t Af[2][4];
            uint32_t Bf[4][4];
#pragma unroll
            for (int mt = 0; mt < 2; mt++) {
                int rl = wm * 32 + mt * 16 + ((j & 1) << 3) + r8;
                int cc = ks * 2 + (j >> 1);
                int ph = cc ^ ((rl >> 1) & 3);
                ldmatrix_x4(Af[mt], ab + rl * 64 + ph * 16);
            }
#pragma unroll
            for (int np = 0; np < 4; np++) {
                int nl = wn * 64 + np * 16 + ((j >> 1) << 3) + r8;
                int cc = ks * 2 + (j & 1);
                int ph = cc ^ ((nl >> 1) & 3);
                ldmatrix_x4(Bf[np], bb + nl * 64 + ph * 16);
            }
#pragma unroll
            for (int np = 0; np < 4; np++) {
#pragma unroll
                for (int mt = 0; mt < 2; mt++) {
                    mma_bf16(acc[mt][2 * np],     Af[mt], Bf[np][0], Bf[np][1]);
                    mma_bf16(acc[mt][2 * np + 1], Af[mt], Bf[np][2], Bf[np][3]);
                }
            }
        }
    }

    // ---- epilogue: smem-staged coalesced writeout ----
    // After the s=7 barrier all warps finished reading buffers 0..2; only
    // buffer 3 (stage 7, 48K..64K) is still live. Stage tile at +0 (34.8KB,
    // spans buffers 0..2 partially), cmax stage at +40K (inside buffer 2).
    __half* stage = reinterpret_cast<__half*>(dsm);                 // [128][SSTR]
    __half* cmst  = reinterpret_cast<__half*>(dsm + 40960);         // [128][16]

    const int g  = lane >> 2;
    const int t4 = lane & 3;
    const int b0  = m0 / Q_;
    const int bnd = (b0 + 1) * Q_;

    // Phase 1: acc -> stage (272B row stride: conflict-free)
#pragma unroll
    for (int mt = 0; mt < 2; mt++) {
        const int rl = wm * 32 + mt * 16 + g;
#pragma unroll
        for (int nt = 0; nt < 8; nt++) {
            int cl = wn * 64 + nt * 8 + t4 * 2;
            *reinterpret_cast<__half2*>(stage + rl * SSTR + cl) =
                __floats2half2_rn(acc[mt][nt][0], acc[mt][nt][1]);
            *reinterpret_cast<__half2*>(stage + (rl + 8) * SSTR + cl) =
                __floats2half2_rn(acc[mt][nt][2], acc[mt][nt][3]);
        }
    }
    __syncthreads();

    // Phase 2: per 8-col chunk: coalesced 16B prob store + hmax + batch max
    float mx0 = 0.0f, mx1 = 0.0f;   // probs > 0; 0 is a safe identity
#pragma unroll
    for (int it = 0; it < 8; it++) {
        int ci = tid + it * 256;        // 0..2047
        int r  = ci >> 4;
        int cp = ci & 15;
        uint4 v = *reinterpret_cast<uint4*>(stage + r * SSTR + cp * 8);
        const __half2* hh = reinterpret_cast<const __half2*>(&v);
        __half2 m2 = __hmax2(__hmax2(hh[0], hh[1]), __hmax2(hh[2], hh[3]));
        __half  m  = __hmax(__low2half(m2), __high2half(m2));
        cmst[ci] = m;
        float fm = __half2float(m);
        if (m0 + r >= bnd) mx1 = fmaxf(mx1, fm); else mx0 = fmaxf(mx0, fm);
        int gcol = l0 + cp * 8;
        if (gcol < LP)      // by<6: always; by=6: only cp=0 (writes 768..775)
            *reinterpret_cast<uint4*>(g_prob_h + (size_t)(m0 + r) * LP + gcol) = v;
    }
#pragma unroll
    for (int o = 16; o > 0; o >>= 1) {
        mx0 = fmaxf(mx0, __shfl_xor_sync(0xFFFFFFFFu, mx0, o));
        mx1 = fmaxf(mx1, __shfl_xor_sync(0xFFFFFFFFu, mx1, o));
    }
    __syncthreads();   // cmst complete
    if (lane == 0) {
        atomicMax(&s_mx0, __float_as_uint(mx0));
        if (bnd < m0 + 128) atomicMax(&s_mx1, __float_as_uint(mx1));
    }
    // coalesced cmax writeout
    {
        int r   = tid >> 1;
        int hf  = tid & 1;
        int chb = (l0 >> 3) + hf * 8;
        if (chb + 8 <= CPAD)
            *reinterpret_cast<uint4*>(g_cmax + (size_t)(m0 + r) * CPAD + chb) =
                *reinterpret_cast<uint4*>(cmst + r * 16 + hf * 8);
    }
    __syncthreads();
    if (tid == 0) {
        atomicMax(&g_maxbits[b0], s_mx0);
        if (bnd < m0 + 128) atomicMax(&g_maxbits[b0 + 1], s_mx1);
    }
}

// ---------------------------------------------------------------------------
// Kernel 3: exact ladder over chunk-maxes (12MB). grid (64, 4).
// ---------------------------------------------------------------------------
__global__ __launch_bounds__(256) void cmax_scan_kernel() {
    const int b    = blockIdx.x;
    const int part = blockIdx.y;
    const int tid  = threadIdx.x;
    const float mx = __uint_as_float(g_maxbits[b]);
    const float lo = mx - 8.0f;
    __shared__ unsigned h[NSL];
    if (tid < NSL) h[tid] = 0u;
    __syncthreads();

    const int r0 = part * 225;                  // 4 x 225 = 900 rows
    const int n  = 225 * (CPAD / 8);            // uint4 per part (13 per row)
    for (int i = tid; i < n; i += 256) {
        int r  = i / 13;
        int c4 = i - r * 13;
        const uint4 v = reinterpret_cast<const uint4*>(
            g_cmax + (size_t)(b * Q_ + r0 + r) * CPAD)[c4];
        const __half2* hh = reinterpret_cast<const __half2*>(&v);
#pragma unroll
        for (int e = 0; e < 4; e++) {
            float2 f2 = __half22float2(hh[e]);
            float fs[2] = {f2.x, f2.y};
#pragma unroll
            for (int u = 0; u < 2; u++) {
                float f = fs[u];
                if (f > lo) {
                    int k = (int)((mx - f) * 4.0f);
                    k = k < 0 ? 0 : (k > NSL - 1 ? NSL - 1 : k);
                    atomicAdd(&h[k], 1u);
                }
            }
        }
    }
    __syncthreads();
    if (tid < NSL && h[tid]) atomicAdd(&g_scnt[b][tid], h[tid]);
}

// ---------------------------------------------------------------------------
// Kernel 4: cmax-gated collect (computes tau in-block from the ladder).
// grid (64, 12).
// ---------------------------------------------------------------------------
#define ROWS_PER_PART 75

__global__ __launch_bounds__(256) void collect_kernel() {
    const int b    = blockIdx.x;
    const int part = blockIdx.y;
    __shared__ float s_tauv;
    if (threadIdx.x == 0) {
        float mx = __uint_as_float(g_maxbits[b]);
        float t = mx - 8.0f;
        unsigned cum = 0;
#pragma unroll
        for (int k = 0; k < NSL; k++) {
            cum += g_scnt[b][k];
            if (cum >= CMINC) { t = mx - 0.25f * (k + 1); break; }
        }
        g_tau[b] = t;    // redundant identical writes from 12 blocks: benign
        s_tauv = t;
    }
    __syncthreads();
    const __half tau = __float2half_rd(s_tauv);

    const int n = ROWS_PER_PART * NCH;
    for (int i = threadIdx.x; i < n; i += 256) {
        int r = i / NCH;
        int c = i - r * NCH;
        int q = part * ROWS_PER_PART + r;
        __half cm = g_cmax[(size_t)(b * Q_ + q) * CPAD + c];
        if (__hge(cm, tau)) {
            const uint4 v = reinterpret_cast<const uint4*>(
                g_prob_h + (size_t)(b * Q_ + q) * LP)[c];
            const __half2* hh = reinterpret_cast<const __half2*>(&v);
#pragma unroll
            for (int e = 0; e < 4; e++) {
                __half lo = __low2half(hh[e]), hi = __high2half(hh[e]);
                if (__hge(lo, tau)) {
                    int p = atomicAdd(&g_ccnt[b], 1);
                    if (p < CCAP) {
                        g_cand[b][p] = q * L_ + c * 8 + e * 2;
                        g_cval[b][p] = lo;
                    }
                }
                if (__hge(hi, tau)) {
                    int p = atomicAdd(&g_ccnt[b], 1);
                    if (p < CCAP) {
                        g_cand[b][p] = q * L_ + c * 8 + e * 2 + 1;
                        g_cval[b][p] = hi;
                    }
                }
            }
        }
    }
}

// ---------------------------------------------------------------------------
// Kernel 4b: fixup loop — re-collect until 64 <= K <= CCAP (normally noop).
// ---------------------------------------------------------------------------
__global__ __launch_bounds__(1024) void fixup_kernel() {
    const int b   = blockIdx.x;
    const int tid = threadIdx.x;
    __shared__ float s_tau;
    for (int iter = 0; iter < 8; iter++) {
        __syncthreads();
        int K = g_ccnt[b];
        if (K >= 64 && K <= CCAP) return;
        if (tid == 0) {
            float t = g_tau[b] + (K > CCAP ? 0.25f : -2.0f);
            g_tau[b] = t;
            g_ccnt[b] = 0;
            s_tau = t;
        }
        __syncthreads();
        const __half htau = __float2half_rd(s_tau);
        for (int i = tid; i < Q_ * L_; i += 1024) {
            int q = i / L_;
            int l = i - q * L_;
            __half v = g_prob_h[(size_t)(b * Q_ + q) * LP + l];
            if (__hge(v, htau)) {
                int p = atomicAdd(&g_ccnt[b], 1);
                if (p < CCAP) { g_cand[b][p] = i; g_cval[b][p] = v; }
            }
        }
    }
}

// ---------------------------------------------------------------------------
// Kernel 5: approx-select + fp32 rescore + exact-select + rank + epilogue.
// ---------------------------------------------------------------------------
__global__ __launch_bounds__(1024) void final_kernel(
    const float* __restrict__ logits, const float* __restrict__ bbox,
    const float* __restrict__ tsz, float* __restrict__ out,
    const float* __restrict__ posmap)
{
    extern __shared__ char fsm[];
    float* s_av  = reinterpret_cast<float*>(fsm);                 // [CCAP]
    int*   s_idx = reinterpret_cast<int*>(fsm + CCAP * 4);        // [CCAP]
    int*   r_idx = reinterpret_cast<int*>(fsm + CCAP * 8);        // [CCAP]
    float* r_ev  = s_av;                                          // alias
    __shared__ unsigned hist[128];
    __shared__ int   s_rcnt, s_r2cnt;
    __shared__ float s_tr, s_estar;
    __shared__ int   r2_idx[RS2_CAP];
    __shared__ float r2_ev[RS2_CAP];

    const int b    = blockIdx.x;
    const int tid  = threadIdx.x;
    const int wid  = tid >> 5;
    const int lane = tid & 31;
    const float tau = g_tau[b];

    int K = g_ccnt[b];
    if (K > CCAP) K = CCAP;

    // Phase A: load candidates + approx histogram over [tau, tau+8)
    for (int i = tid; i < 128; i += 1024) hist[i] = 0u;
    if (tid == 0) { s_rcnt = 0; s_r2cnt = 0; }
    __syncthreads();
    for (int c = tid; c < K; c += 1024) {
        float v = __half2float(g_cval[b][c]);
        s_av[c]  = v;
        s_idx[c] = g_cand[b][c];
        int bin = (int)((v - tau) * 16.0f);
        bin = bin < 0 ? 0 : (bin > 127 ? 127 : bin);
        atomicAdd(&hist[bin], 1u);
    }
    __syncthreads();

    // Phase B: approx 50th edge; rescore threshold = edge - 1.0
    if (tid == 0) {
        unsigned cum = 0;
        int bstar = 0;
        for (int k = 127; k >= 0; k--) {
            cum += hist[k];
            if (cum >= NSEL) { bstar = k; break; }
        }
        s_tr = tau + bstar * (1.0f / 16.0f) - 1.0f;
    }
    __syncthreads();
    const float tr = s_tr;

    // Phase C: compact rescore set
    for (int c = tid; c < K; c += 1024) {
        if (s_av[c] >= tr) {
            int p = atomicAdd(&s_rcnt, 1);
            if (p < CCAP) r_idx[p] = s_idx[c];
        }
    }
    __syncthreads();
    int R = s_rcnt < CCAP ? s_rcnt : CCAP;

    // Phase D: fp32 rescore (one warp per candidate)
    for (int c = wid; c < R; c += 32) {
        int idx = r_idx[c];
        int q = idx / L_;
        int l = idx - q * L_;
        const float4* a = reinterpret_cast<const float4*>(
            logits + (size_t)(b * Q_ + q) * T_ + lane * 8);
        const float4* p = reinterpret_cast<const float4*>(
            posmap + (size_t)l * T_ + lane * 8);
        float4 a0 = a[0], a1 = a[1], p0 = p[0], p1 = p[1];
        float s = sigf(a0.x) * p0.x + sigf(a0.y) * p0.y
                + sigf(a0.z) * p0.z + sigf(a0.w) * p0.w
                + sigf(a1.x) * p1.x + sigf(a1.y) * p1.y
                + sigf(a1.z) * p1.z + sigf(a1.w) * p1.w;
#pragma unroll
        for (int o = 16; o > 0; o >>= 1) s += __shfl_xor_sync(0xFFFFFFFFu, s, o);
        if (lane == 0) r_ev[c] = s;
    }
    __syncthreads();

    // Phase E: exact histogram over [tr-1, tr+7); exact 50th edge
    for (int i = tid; i < 128; i += 1024) hist[i] = 0u;
    __syncthreads();
    const float base = tr - 1.0f;
    for (int c = tid; c < R; c += 1024) {
        int bin = (int)((r_ev[c] - base) * 16.0f);
        bin = bin < 0 ? 0 : (bin > 127 ? 127 : bin);
        atomicAdd(&hist[bin], 1u);
    }
    __syncthreads();
    if (tid == 0) {
        unsigned cum = 0;
        int eb = 0;
        for (int k = 127; k >= 0; k--) {
            cum += hist[k];
            if (cum >= NSEL) { eb = k; break; }
        }
        s_estar = base + eb * (1.0f / 16.0f);
    }
    __syncthreads();
    const float estar = s_estar;

    // Phase F: compact exact finalists
    for (int c = tid; c < R; c += 1024) {
        if (r_ev[c] >= estar) {
            int p = atomicAdd(&s_r2cnt, 1);
            if (p < RS2_CAP) { r2_idx[p] = r_idx[c]; r2_ev[p] = r_ev[c]; }
        }
    }
    __syncthreads();
    int R2 = s_r2cnt < RS2_CAP ? s_r2cnt : RS2_CAP;

    // Phase G: exact rank (value desc, index asc) + epilogue
    for (int jj = tid; jj < R2; jj += 1024) {
        float vj = r2_ev[jj];
        int   ij = r2_idx[jj];
        int rank = 0;
        for (int i = 0; i < R2; i++) {
            float vi = r2_ev[i];
            int   ii = r2_idx[i];
            if (vi > vj || (vi == vj && ii < ij)) rank++;
        }
        if (rank < NSEL) {
            int o = b * NSEL + rank;
            out[o] = vj;
            int q = ij / L_;
            int l = ij - q * L_;
            int label = 0;
#pragma unroll
            for (int t = 0; t < 80; t++)
                if (c_tok[t] == l) label = t;
            out[B_ * NSEL + o] = (float)label;
            const float* bb = bbox + (size_t)(b * Q_ + q) * 4;
            float cx = bb[0], cy = bb[1], w = bb[2], h = bb[3];
            float ih = tsz[2 * b + 0], iw = tsz[2 * b + 1];
            float* ob = out + 2 * B_ * NSEL + (size_t)o * 4;
            ob[0] = (cx - 0.5f * w) * iw;
            ob[1] = (cy - 0.5f * h) * ih;
            ob[2] = (cx + 0.5f * w) * iw;
            ob[3] = (cy + 0.5f * h) * ih;
        }
    }
}

// ---------------------------------------------------------------------------
extern "C" void kernel_launch(void* const* d_in, const int* in_sizes, int n_in,
                              void* d_out, int out_size) {
    const float* logits = (const float*)d_in[0];
    const float* bbox   = (const float*)d_in[1];
    const float* posmap = (const float*)d_in[2];
    const float* tsz    = (const float*)d_in[3];
    float* out = (float*)d_out;

    cudaFuncSetAttribute(gemm_kernel,
        cudaFuncAttributeMaxDynamicSharedMemorySize, NBUF * STG_BYTES);
    cudaFuncSetAttribute(final_kernel,
        cudaFuncAttributeMaxDynamicSharedMemorySize, CCAP * 12);

    zero_kernel<<<2, 1024>>>();

    const int n4 = (M_ * T_) / 4;
    sigmoid_kernel<<<(n4 + 255) / 256, 256>>>(logits, n4);
    posconv_kernel<<<(L_ * T_ / 2 + 255) / 256, 256>>>(posmap, L_ * T_ / 2);

    dim3 ggrid(M_ / 128, (L_ + 127) / 128);   // 450 x 7
    gemm_kernel<<<ggrid, 256, NBUF * STG_BYTES>>>();

    dim3 sgrid(B_, 4);
    cmax_scan_kernel<<<sgrid, 256>>>();
    dim3 cgrid(B_, 12);
    collect_kernel<<<cgrid, 256>>>();
    fixup_kernel<<<B_, 1024>>>();
    final_kernel<<<B_, 1024, CCAP * 12>>>(logits, bbox, tsz, out, posmap);
}